// round 7
// baseline (speedup 1.0000x reference)
#include <cuda_runtime.h>
#include <math.h>

#define B_  4
#define S_  2048
#define D_  1280
#define H_  16
#define HD_ 80
#define NQKV (3 * H_ * HD_)   // 3840

// Scratch (allocation-free rule: __device__ globals)
__device__ float g_qkv[(size_t)B_ * S_ * NQKV];        // 126 MB
__device__ float g_attn[(size_t)B_ * S_ * H_ * HD_];   // 42 MB
__device__ float g_qscale[HD_];

// ---------------------------------------------------------------------------
// Helpers: tf32 rounding + mma
// ---------------------------------------------------------------------------
__device__ __forceinline__ unsigned f2tf(float x) {
    unsigned r;
    asm("cvt.rna.tf32.f32 %0, %1;" : "=r"(r) : "f"(x));
    return r;
}
__device__ __forceinline__ float f2tff(float x) {
    return __uint_as_float(f2tf(x));
}
__device__ __forceinline__ void mma_tf32(float* d, const unsigned* a,
                                         unsigned b0, unsigned b1) {
    asm volatile(
        "mma.sync.aligned.m16n8k8.row.col.f32.tf32.tf32.f32 "
        "{%0,%1,%2,%3}, {%4,%5,%6,%7}, {%8,%9}, {%0,%1,%2,%3};"
        : "+f"(d[0]), "+f"(d[1]), "+f"(d[2]), "+f"(d[3])
        : "r"(a[0]), "r"(a[1]), "r"(a[2]), "r"(a[3]), "r"(b0), "r"(b1));
}

// ---------------------------------------------------------------------------
// Per-dim query scale: softplus(scaling) * log2(e) / sqrt(HD)
// ---------------------------------------------------------------------------
__global__ void qscale_kernel(const float* __restrict__ scaling) {
    int i = threadIdx.x;
    if (i < HD_) {
        float x = scaling[i];
        float sp = (x > 20.f) ? x : log1pf(expf(x));
        g_qscale[i] = sp * 1.4426950408889634f * rsqrtf((float)HD_);
    }
}

// ---------------------------------------------------------------------------
// TF32 tensor-core GEMM: C = A·B^T + bias  (both K-major)
// 128x128 tile, KT=16, 256 threads, warp tile 32x64, m16n8k8.tf32.
// DOUBLE-BUFFERED smem: one __syncthreads per iteration; STS targets the
// inactive buffer while HMMAs consume the active one.
// ---------------------------------------------------------------------------
#define SMS 136
#define STAGE (16 * SMS)   // floats per stage per operand

template <int APPLY_QSCALE>
__global__ __launch_bounds__(256, 2)
void gemm_tf32(const float* __restrict__ A, const float* __restrict__ Bm,
               const float* __restrict__ bias, float* __restrict__ C,
               int M, int N, int K) {
    __shared__ float As[2 * STAGE];
    __shared__ float Bs[2 * STAGE];

    const int tid  = threadIdx.x;
    const int lane = tid & 31;
    const int wid  = tid >> 5;
    const int wm   = wid & 3;
    const int wn   = wid >> 2;
    const int g    = lane >> 2;
    const int c    = lane & 3;

    const int m0 = blockIdx.y * 128;
    const int n0 = blockIdx.x * 128;

    const int lrow = tid >> 1;
    const int lc   = (tid & 1) * 8;

    const float* Ap = A  + (size_t)(m0 + lrow) * K + lc;
    const float* Bp = Bm + (size_t)(n0 + lrow) * K + lc;

    float acc[2][8][4];
#pragma unroll
    for (int i = 0; i < 2; ++i)
#pragma unroll
        for (int j = 0; j < 8; ++j)
#pragma unroll
            for (int q = 0; q < 4; ++q) acc[i][j][q] = 0.f;

    // load + store tile 0 into stage 0
    float4 pa0 = *(const float4*)(Ap + 0);
    float4 pa1 = *(const float4*)(Ap + 4);
    float4 pb0 = *(const float4*)(Bp + 0);
    float4 pb1 = *(const float4*)(Bp + 4);
    {
        float* as = &As[lc * SMS + lrow];
        as[0 * SMS] = f2tff(pa0.x); as[1 * SMS] = f2tff(pa0.y);
        as[2 * SMS] = f2tff(pa0.z); as[3 * SMS] = f2tff(pa0.w);
        as[4 * SMS] = f2tff(pa1.x); as[5 * SMS] = f2tff(pa1.y);
        as[6 * SMS] = f2tff(pa1.z); as[7 * SMS] = f2tff(pa1.w);
        float* bs = &Bs[lc * SMS + lrow];
        bs[0 * SMS] = f2tff(pb0.x); bs[1 * SMS] = f2tff(pb0.y);
        bs[2 * SMS] = f2tff(pb0.z); bs[3 * SMS] = f2tff(pb0.w);
        bs[4 * SMS] = f2tff(pb1.x); bs[5 * SMS] = f2tff(pb1.y);
        bs[6 * SMS] = f2tff(pb1.z); bs[7 * SMS] = f2tff(pb1.w);
    }
    __syncthreads();

    int p = 0;
    for (int k0 = 0; k0 < K; k0 += 16) {
        const bool more = (k0 + 16) < K;
        if (more) {   // prefetch next tile into registers
            pa0 = *(const float4*)(Ap + k0 + 16);
            pa1 = *(const float4*)(Ap + k0 + 20);
            pb0 = *(const float4*)(Bp + k0 + 16);
            pb1 = *(const float4*)(Bp + k0 + 20);
        }

        const float* Asp = &As[p * STAGE];
        const float* Bsp = &Bs[p * STAGE];
#pragma unroll
        for (int ks = 0; ks < 2; ++ks) {
            const int kk = ks * 8;
            unsigned af[2][4];
#pragma unroll
            for (int i = 0; i < 2; ++i) {
                const float* ab = &Asp[(kk + c) * SMS + wm * 32 + i * 16 + g];
                af[i][0] = __float_as_uint(ab[0]);
                af[i][1] = __float_as_uint(ab[8]);
                af[i][2] = __float_as_uint(ab[4 * SMS]);
                af[i][3] = __float_as_uint(ab[4 * SMS + 8]);
            }
#pragma unroll
            for (int j = 0; j < 8; ++j) {
                const float* bb = &Bsp[(kk + c) * SMS + wn * 64 + j * 8 + g];
                unsigned b0 = __float_as_uint(bb[0]);
                unsigned b1 = __float_as_uint(bb[4 * SMS]);
                mma_tf32(acc[0][j], af[0], b0, b1);
                mma_tf32(acc[1][j], af[1], b0, b1);
            }
        }

        if (more) {   // store prefetched tile into the inactive stage
            float* as = &As[(p ^ 1) * STAGE + lc * SMS + lrow];
            as[0 * SMS] = f2tff(pa0.x); as[1 * SMS] = f2tff(pa0.y);
            as[2 * SMS] = f2tff(pa0.z); as[3 * SMS] = f2tff(pa0.w);
            as[4 * SMS] = f2tff(pa1.x); as[5 * SMS] = f2tff(pa1.y);
            as[6 * SMS] = f2tff(pa1.z); as[7 * SMS] = f2tff(pa1.w);
            float* bs = &Bs[(p ^ 1) * STAGE + lc * SMS + lrow];
            bs[0 * SMS] = f2tff(pb0.x); bs[1 * SMS] = f2tff(pb0.y);
            bs[2 * SMS] = f2tff(pb0.z); bs[3 * SMS] = f2tff(pb0.w);
            bs[4 * SMS] = f2tff(pb1.x); bs[5 * SMS] = f2tff(pb1.y);
            bs[6 * SMS] = f2tff(pb1.z); bs[7 * SMS] = f2tff(pb1.w);
        }
        __syncthreads();
        p ^= 1;
    }

#pragma unroll
    for (int j = 0; j < 8; ++j) {
        const int col = n0 + wn * 64 + j * 8 + c * 2;
        float b0 = bias[col], b1 = bias[col + 1];
        float q0 = 1.f, q1 = 1.f;
        if (APPLY_QSCALE && col < H_ * HD_) {
            q0 = g_qscale[col % HD_];
            q1 = g_qscale[(col + 1) % HD_];
        }
#pragma unroll
        for (int i = 0; i < 2; ++i) {
            const int r0 = m0 + wm * 32 + i * 16 + g;
            float2 o0, o1;
            o0.x = (acc[i][j][0] + b0) * q0;
            o0.y = (acc[i][j][1] + b1) * q1;
            o1.x = (acc[i][j][2] + b0) * q0;
            o1.y = (acc[i][j][3] + b1) * q1;
            *(float2*)&C[(size_t)r0 * N + col]       = o0;
            *(float2*)&C[(size_t)(r0 + 8) * N + col] = o1;
        }
    }
}

// ---------------------------------------------------------------------------
// Tensor-core causal flash attention (tf32 HMMA, FA2-style).
// BQ=64 (4 warps x 16 rows), BK=64. K/V staged fragment-major with EVEN
// stride 22 so B-fragment pairs load as aligned LDS.64 (bank: (11*row+kt)
// mod 32 distinct per phase). P re-fragmented via warp-private smem.
// grid = (S/64 [reversed], H, B), block = 128.
// ---------------------------------------------------------------------------
#define KV_ST 22
#define P_ST  68
#define QS_ST 84
#define QS_FLOATS (64 * QS_ST)          // 5376
#define KF_FLOATS (64 * 4 * KV_ST)      // 5632
#define VF_FLOATS (80 * 4 * KV_ST)      // 7040 (n-indexed: 80 features)
#define FL_SMEM_FLOATS (QS_FLOATS + KF_FLOATS + VF_FLOATS)   // 18048

__global__ __launch_bounds__(128, 2)
void flash_tc() {
    extern __shared__ float sm[];
    float* Qs = sm;                     // [64][84]; reused as P
    float* Kf = sm + QS_FLOATS;
    float* Vf = Kf + KF_FLOATS;

    const int t    = threadIdx.x;
    const int lane = t & 31;
    const int wq   = t >> 5;
    const int g    = lane >> 2;
    const int c    = lane & 3;
    const int qt   = gridDim.x - 1 - blockIdx.x;   // heavy blocks first
    const int q0   = qt * 64;
    const int h    = blockIdx.y;
    const int b    = blockIdx.z;

    const float4* qkv4 = (const float4*)g_qkv;     // row stride 960

    // Stage Q (tf32-rounded) into Qs[64][84]
    for (int i = t; i < 64 * 20; i += 128) {
        int r = i / 20, q = i % 20;
        float4 v = qkv4[(size_t)(b * S_ + q0 + r) * 960 + h * 20 + q];
        float* dst = &Qs[r * QS_ST + q * 4];
        dst[0] = f2tff(v.x); dst[1] = f2tff(v.y);
        dst[2] = f2tff(v.z); dst[3] = f2tff(v.w);
    }
    __syncthreads();

    // Q fragments (A layout)
    unsigned qf[10][4];
#pragma unroll
    for (int kt = 0; kt < 10; ++kt) {
        const float* qp = &Qs[(wq * 16 + g) * QS_ST + kt * 8 + c];
        qf[kt][0] = __float_as_uint(qp[0]);
        qf[kt][1] = __float_as_uint(qp[8 * QS_ST]);
        qf[kt][2] = __float_as_uint(qp[4]);
        qf[kt][3] = __float_as_uint(qp[8 * QS_ST + 4]);
    }

    float m0 = -INFINITY, m1 = -INFINITY, l0 = 0.f, l1 = 0.f;
    float o[10][4];
#pragma unroll
    for (int j = 0; j < 10; ++j)
#pragma unroll
        for (int q = 0; q < 4; ++q) o[j][q] = 0.f;

    float* Pw = sm + wq * (16 * P_ST);   // warp-private, overlaps Qs (safe)

    const int ntiles = qt + 1;
    for (int kt0 = 0; kt0 < ntiles; ++kt0) {
        const int k0 = kt0 * 64;
        __syncthreads();
        for (int i = t; i < 64 * 20; i += 128) {
            int r = i / 20, q = i % 20;
            size_t base = (size_t)(b * S_ + k0 + r) * 960 + h * 20 + q;
            float4 kv = qkv4[base + 320];
            float* kd = &Kf[(r * 4) * KV_ST + q];   // K[r][4q+e] -> (r*4+e)*22+q
            kd[0 * KV_ST] = f2tff(kv.x);
            kd[1 * KV_ST] = f2tff(kv.y);
            kd[2 * KV_ST] = f2tff(kv.z);
            kd[3 * KV_ST] = f2tff(kv.w);
            float4 vv = qkv4[base + 640];
            int vb = (r & 3) * KV_ST + (r >> 2);    // V[r][n] -> (n*4+r%4)*22+r/4
            Vf[(4 * q + 0) * 4 * KV_ST + vb] = f2tff(vv.x);
            Vf[(4 * q + 1) * 4 * KV_ST + vb] = f2tff(vv.y);
            Vf[(4 * q + 2) * 4 * KV_ST + vb] = f2tff(vv.z);
            Vf[(4 * q + 3) * 4 * KV_ST + vb] = f2tff(vv.w);
        }
        __syncthreads();

        // ---- S = Q K^T (LDS.64 B-fragments) ----
        float s[8][4];
#pragma unroll
        for (int j = 0; j < 8; ++j)
#pragma unroll
            for (int q = 0; q < 4; ++q) s[j][q] = 0.f;
#pragma unroll
        for (int kt = 0; kt < 10; ++kt)
#pragma unroll
            for (int j = 0; j < 8; ++j) {
                float2 kk = *(const float2*)
                    &Kf[((j * 8 + g) * 4 + c) * KV_ST + 2 * kt];
                mma_tf32(s[j], qf[kt],
                         __float_as_uint(kk.x), __float_as_uint(kk.y));
            }

        // ---- causal mask (diagonal tile only) ----
        if (k0 == q0) {
            const int row0 = wq * 16 + g;
#pragma unroll
            for (int j = 0; j < 8; ++j) {
                const int col = j * 8 + 2 * c;
                if (col     > row0)     s[j][0] = -INFINITY;
                if (col + 1 > row0)     s[j][1] = -INFINITY;
                if (col     > row0 + 8) s[j][2] = -INFINITY;
                if (col + 1 > row0 + 8) s[j][3] = -INFINITY;
            }
        }

        // ---- online softmax (rows g, g+8; quad shuffles) ----
        float tm0 = -INFINITY, tm1 = -INFINITY;
#pragma unroll
        for (int j = 0; j < 8; ++j) {
            tm0 = fmaxf(tm0, fmaxf(s[j][0], s[j][1]));
            tm1 = fmaxf(tm1, fmaxf(s[j][2], s[j][3]));
        }
        tm0 = fmaxf(tm0, __shfl_xor_sync(0xffffffff, tm0, 1));
        tm0 = fmaxf(tm0, __shfl_xor_sync(0xffffffff, tm0, 2));
        tm1 = fmaxf(tm1, __shfl_xor_sync(0xffffffff, tm1, 1));
        tm1 = fmaxf(tm1, __shfl_xor_sync(0xffffffff, tm1, 2));
        float nm0 = fmaxf(m0, tm0), nm1 = fmaxf(m1, tm1);
        float cr0 = __expf(m0 - nm0), cr1 = __expf(m1 - nm1);
        m0 = nm0; m1 = nm1;
        float ls0 = 0.f, ls1 = 0.f;
#pragma unroll
        for (int j = 0; j < 8; ++j) {
            s[j][0] = __expf(s[j][0] - m0);
            s[j][1] = __expf(s[j][1] - m0);
            s[j][2] = __expf(s[j][2] - m1);
            s[j][3] = __expf(s[j][3] - m1);
            ls0 += s[j][0] + s[j][1];
            ls1 += s[j][2] + s[j][3];
        }
        ls0 += __shfl_xor_sync(0xffffffff, ls0, 1);
        ls0 += __shfl_xor_sync(0xffffffff, ls0, 2);
        ls1 += __shfl_xor_sync(0xffffffff, ls1, 1);
        ls1 += __shfl_xor_sync(0xffffffff, ls1, 2);
        l0 = l0 * cr0 + ls0;
        l1 = l1 * cr1 + ls1;
#pragma unroll
        for (int j = 0; j < 10; ++j) {
            o[j][0] *= cr0; o[j][1] *= cr0;
            o[j][2] *= cr1; o[j][3] *= cr1;
        }

        // ---- P round trip: C-fragment -> warp smem -> A-fragment ----
        __syncwarp();
#pragma unroll
        for (int j = 0; j < 8; ++j) {
            *(float2*)&Pw[g * P_ST + j * 8 + 2 * c] =
                make_float2(f2tff(s[j][0]), f2tff(s[j][1]));
            *(float2*)&Pw[(g + 8) * P_ST + j * 8 + 2 * c] =
                make_float2(f2tff(s[j][2]), f2tff(s[j][3]));
        }
        __syncwarp();
        unsigned pa[8][4];
#pragma unroll
        for (int kt = 0; kt < 8; ++kt) {
            const float* pp = &Pw[g * P_ST + kt * 8 + c];
            pa[kt][0] = __float_as_uint(pp[0]);
            pa[kt][1] = __float_as_uint(pp[8 * P_ST]);
            pa[kt][2] = __float_as_uint(pp[4]);
            pa[kt][3] = __float_as_uint(pp[8 * P_ST + 4]);
        }

        // ---- O += P V (LDS.64 B-fragments) ----
#pragma unroll
        for (int kt = 0; kt < 8; ++kt)
#pragma unroll
            for (int j = 0; j < 10; ++j) {
                float2 vv = *(const float2*)
                    &Vf[((j * 8 + g) * 4 + c) * KV_ST + 2 * kt];
                mma_tf32(o[j], pa[kt],
                         __float_as_uint(vv.x), __float_as_uint(vv.y));
            }
    }

    // ---- epilogue: normalize, write g_attn ----
    const float inv0 = 1.f / l0, inv1 = 1.f / l1;
    const int r0 = q0 + wq * 16 + g;
    float* outp = g_attn + (size_t)(b * S_ + r0) * (H_ * HD_) + h * HD_;
#pragma unroll
    for (int j = 0; j < 10; ++j) {
        *(float2*)&outp[j * 8 + 2 * c] =
            make_float2(o[j][0] * inv0, o[j][1] * inv0);
        *(float2*)&outp[(size_t)8 * (H_ * HD_) + j * 8 + 2 * c] =
            make_float2(o[j][2] * inv1, o[j][3] * inv1);
    }
}

// ---------------------------------------------------------------------------
// Launch
// ---------------------------------------------------------------------------
extern "C" void kernel_launch(void* const* d_in, const int* in_sizes, int n_in,
                              void* d_out, int out_size) {
    const float* hidden  = (const float*)d_in[0];
    // d_in[1] = attention_mask: pure causal, implemented structurally
    const float* scaling = (const float*)d_in[2];
    const float* qkv_w   = (const float*)d_in[3];
    const float* qkv_b   = (const float*)d_in[4];
    const float* o_w     = (const float*)d_in[5];
    const float* o_b     = (const float*)d_in[6];
    float* out = (float*)d_out;

    void* p_qkv = nullptr;
    void* p_attn = nullptr;
    cudaGetSymbolAddress(&p_qkv, g_qkv);
    cudaGetSymbolAddress(&p_attn, g_attn);

    qscale_kernel<<<1, 128>>>(scaling);

    // QKV projection: [8192,1280] x [3840,1280]^T (+bias, Q-scale epilogue)
    gemm_tf32<1><<<dim3(NQKV / 128, (B_ * S_) / 128), 256>>>(
        hidden, qkv_w, qkv_b, (float*)p_qkv, B_ * S_, NQKV, D_);

    // Tensor-core causal flash attention
    const int smem_bytes = FL_SMEM_FLOATS * 4;   // 72192 B
    cudaFuncSetAttribute(flash_tc,
                         cudaFuncAttributeMaxDynamicSharedMemorySize, smem_bytes);
    flash_tc<<<dim3(S_ / 64, H_, B_), 128, smem_bytes>>>();

    // Output projection: [8192,1280] x [1280,1280]^T (+bias)
    gemm_tf32<0><<<dim3(D_ / 128, (B_ * S_) / 128), 256>>>(
        (const float*)p_attn, o_w, o_b, out, B_ * S_, D_, D_);
}

// round 8
// speedup vs baseline: 1.1100x; 1.1100x over previous
#include <cuda_runtime.h>
#include <math.h>

#define B_  4
#define S_  2048
#define D_  1280
#define H_  16
#define HD_ 80
#define NQKV (3 * H_ * HD_)   // 3840

// Scratch (allocation-free rule: __device__ globals)
__device__ float g_qkv[(size_t)B_ * S_ * NQKV];        // 126 MB
__device__ float g_attn[(size_t)B_ * S_ * H_ * HD_];   // 42 MB
__device__ float g_qscale[HD_];

// ---------------------------------------------------------------------------
// Helpers: tf32 rounding + mma
// ---------------------------------------------------------------------------
__device__ __forceinline__ unsigned f2tf(float x) {
    unsigned r;
    asm("cvt.rna.tf32.f32 %0, %1;" : "=r"(r) : "f"(x));
    return r;
}
__device__ __forceinline__ float f2tff(float x) {
    return __uint_as_float(f2tf(x));
}
__device__ __forceinline__ void mma_tf32(float* d, const unsigned* a,
                                         unsigned b0, unsigned b1) {
    asm volatile(
        "mma.sync.aligned.m16n8k8.row.col.f32.tf32.tf32.f32 "
        "{%0,%1,%2,%3}, {%4,%5,%6,%7}, {%8,%9}, {%0,%1,%2,%3};"
        : "+f"(d[0]), "+f"(d[1]), "+f"(d[2]), "+f"(d[3])
        : "r"(a[0]), "r"(a[1]), "r"(a[2]), "r"(a[3]), "r"(b0), "r"(b1));
}

// ---------------------------------------------------------------------------
// Per-dim query scale: softplus(scaling) * log2(e) / sqrt(HD)
// ---------------------------------------------------------------------------
__global__ void qscale_kernel(const float* __restrict__ scaling) {
    int i = threadIdx.x;
    if (i < HD_) {
        float x = scaling[i];
        float sp = (x > 20.f) ? x : log1pf(expf(x));
        g_qscale[i] = sp * 1.4426950408889634f * rsqrtf((float)HD_);
    }
}

// ---------------------------------------------------------------------------
// TF32 tensor-core GEMM: C = A·B^T + bias  (both K-major)
// 128x128 tile, KT=16, 256 threads, warp tile 32x64, m16n8k8.tf32.
// Double-buffered. Paired-fragment smem layout: row-major [row][off(k)],
// off(k) = (k&3)*2 + ((k>>2)&1) + (k&8), stride 18 -> fragment pairs
// (k, k+4) adjacent, loaded with LDS.64 (banks 9*row+c, conflict-free).
// ---------------------------------------------------------------------------
#define AST 18
#define STG (128 * AST)   // floats per stage per operand

__device__ __forceinline__ void store_paired(float* dst, float4 lo, float4 hi,
                                             int lc) {
    // lo = k=lc..lc+3, hi = k=lc+4..lc+7; off = lc + 2j (+1 for hi)
    dst[lc + 0] = f2tff(lo.x); dst[lc + 1] = f2tff(hi.x);
    dst[lc + 2] = f2tff(lo.y); dst[lc + 3] = f2tff(hi.y);
    dst[lc + 4] = f2tff(lo.z); dst[lc + 5] = f2tff(hi.z);
    dst[lc + 6] = f2tff(lo.w); dst[lc + 7] = f2tff(hi.w);
}

template <int APPLY_QSCALE>
__global__ __launch_bounds__(256, 2)
void gemm_tf32(const float* __restrict__ A, const float* __restrict__ Bm,
               const float* __restrict__ bias, float* __restrict__ C,
               int M, int N, int K) {
    __shared__ float As[2 * STG];
    __shared__ float Bs[2 * STG];

    const int tid  = threadIdx.x;
    const int lane = tid & 31;
    const int wid  = tid >> 5;
    const int wm   = wid & 3;
    const int wn   = wid >> 2;
    const int g    = lane >> 2;
    const int c    = lane & 3;

    const int m0 = blockIdx.y * 128;
    const int n0 = blockIdx.x * 128;

    const int lrow = tid >> 1;
    const int lc   = (tid & 1) * 8;

    const float* Ap = A  + (size_t)(m0 + lrow) * K + lc;
    const float* Bp = Bm + (size_t)(n0 + lrow) * K + lc;

    float acc[2][8][4];
#pragma unroll
    for (int i = 0; i < 2; ++i)
#pragma unroll
        for (int j = 0; j < 8; ++j)
#pragma unroll
            for (int q = 0; q < 4; ++q) acc[i][j][q] = 0.f;

    // tile 0 -> stage 0
    float4 pa0 = *(const float4*)(Ap + 0);
    float4 pa1 = *(const float4*)(Ap + 4);
    float4 pb0 = *(const float4*)(Bp + 0);
    float4 pb1 = *(const float4*)(Bp + 4);
    store_paired(&As[lrow * AST], pa0, pa1, lc);
    store_paired(&Bs[lrow * AST], pb0, pb1, lc);
    __syncthreads();

    int p = 0;
    for (int k0 = 0; k0 < K; k0 += 16) {
        const bool more = (k0 + 16) < K;
        if (more) {
            pa0 = *(const float4*)(Ap + k0 + 16);
            pa1 = *(const float4*)(Ap + k0 + 20);
            pb0 = *(const float4*)(Bp + k0 + 16);
            pb1 = *(const float4*)(Bp + k0 + 20);
        }

        const float* Asp = &As[p * STG];
        const float* Bsp = &Bs[p * STG];
#pragma unroll
        for (int ks = 0; ks < 2; ++ks) {
            const int kk = ks * 8;
            unsigned af[2][4];
#pragma unroll
            for (int i = 0; i < 2; ++i) {
                const int r0 = wm * 32 + i * 16 + g;
                float2 f0 = *(const float2*)&Asp[r0 * AST + 2 * c + kk];
                float2 f1 = *(const float2*)&Asp[(r0 + 8) * AST + 2 * c + kk];
                af[i][0] = __float_as_uint(f0.x);   // A[g][c]
                af[i][1] = __float_as_uint(f1.x);   // A[g+8][c]
                af[i][2] = __float_as_uint(f0.y);   // A[g][c+4]
                af[i][3] = __float_as_uint(f1.y);   // A[g+8][c+4]
            }
#pragma unroll
            for (int j = 0; j < 8; ++j) {
                const int n = wn * 64 + j * 8 + g;
                float2 fb = *(const float2*)&Bsp[n * AST + 2 * c + kk];
                unsigned b0 = __float_as_uint(fb.x);
                unsigned b1 = __float_as_uint(fb.y);
                mma_tf32(acc[0][j], af[0], b0, b1);
                mma_tf32(acc[1][j], af[1], b0, b1);
            }
        }

        if (more) {
            store_paired(&As[(p ^ 1) * STG + lrow * AST], pa0, pa1, lc);
            store_paired(&Bs[(p ^ 1) * STG + lrow * AST], pb0, pb1, lc);
        }
        __syncthreads();
        p ^= 1;
    }

#pragma unroll
    for (int j = 0; j < 8; ++j) {
        const int col = n0 + wn * 64 + j * 8 + c * 2;
        float b0 = bias[col], b1 = bias[col + 1];
        float q0 = 1.f, q1 = 1.f;
        if (APPLY_QSCALE && col < H_ * HD_) {
            q0 = g_qscale[col % HD_];
            q1 = g_qscale[(col + 1) % HD_];
        }
#pragma unroll
        for (int i = 0; i < 2; ++i) {
            const int r0 = m0 + wm * 32 + i * 16 + g;
            float2 o0, o1;
            o0.x = (acc[i][j][0] + b0) * q0;
            o0.y = (acc[i][j][1] + b1) * q1;
            o1.x = (acc[i][j][2] + b0) * q0;
            o1.y = (acc[i][j][3] + b1) * q1;
            *(float2*)&C[(size_t)r0 * N + col]       = o0;
            *(float2*)&C[(size_t)(r0 + 8) * N + col] = o1;
        }
    }
}

// ---------------------------------------------------------------------------
// Tensor-core causal flash attention (tf32 HMMA, FA2-style).
// BQ=64 (4 warps x 16 rows), BK=64.
// K fragment-major, stride 21 (R6-proven, conflict-free scalar LDS).
// V ROW-MAJOR [r][n], stride 88: float4 STS stores (conflict-free; the
// fragment-major V transpose-scatter was 8..16-way store-conflicted) and
// scalar fragment loads at banks 24c+g (all 32 distinct).
// grid = (S/64 [reversed], H, B), block = 128.
// ---------------------------------------------------------------------------
#define KV_ST 21
#define VS_ST 88
#define P_ST  68
#define QS_ST 84
#define QS_FLOATS (64 * QS_ST)          // 5376
#define KF_FLOATS (64 * 4 * KV_ST)      // 5376
#define VS_FLOATS (64 * VS_ST)          // 5632
#define FL_SMEM_FLOATS (QS_FLOATS + KF_FLOATS + VS_FLOATS)   // 16384

__global__ __launch_bounds__(128, 2)
void flash_tc() {
    extern __shared__ float sm[];
    float* Qs = sm;                     // [64][84]; reused as P
    float* Kf = sm + QS_FLOATS;
    float* Vs = Kf + KF_FLOATS;

    const int t    = threadIdx.x;
    const int lane = t & 31;
    const int wq   = t >> 5;
    const int g    = lane >> 2;
    const int c    = lane & 3;
    const int qt   = gridDim.x - 1 - blockIdx.x;   // heavy blocks first
    const int q0   = qt * 64;
    const int h    = blockIdx.y;
    const int b    = blockIdx.z;

    const float4* qkv4 = (const float4*)g_qkv;     // row stride 960

    // Stage Q (tf32-rounded) into Qs[64][84]
    for (int i = t; i < 64 * 20; i += 128) {
        int r = i / 20, q = i % 20;
        float4 v = qkv4[(size_t)(b * S_ + q0 + r) * 960 + h * 20 + q];
        float* dst = &Qs[r * QS_ST + q * 4];
        dst[0] = f2tff(v.x); dst[1] = f2tff(v.y);
        dst[2] = f2tff(v.z); dst[3] = f2tff(v.w);
    }
    __syncthreads();

    // Q fragments (A layout)
    unsigned qf[10][4];
#pragma unroll
    for (int kt = 0; kt < 10; ++kt) {
        const float* qp = &Qs[(wq * 16 + g) * QS_ST + kt * 8 + c];
        qf[kt][0] = __float_as_uint(qp[0]);
        qf[kt][1] = __float_as_uint(qp[8 * QS_ST]);
        qf[kt][2] = __float_as_uint(qp[4]);
        qf[kt][3] = __float_as_uint(qp[8 * QS_ST + 4]);
    }

    float m0 = -INFINITY, m1 = -INFINITY, l0 = 0.f, l1 = 0.f;
    float o[10][4];
#pragma unroll
    for (int j = 0; j < 10; ++j)
#pragma unroll
        for (int q = 0; q < 4; ++q) o[j][q] = 0.f;

    float* Pw = sm + wq * (16 * P_ST);   // warp-private, overlaps Qs (safe)

    const int ntiles = qt + 1;
    for (int kt0 = 0; kt0 < ntiles; ++kt0) {
        const int k0 = kt0 * 64;
        __syncthreads();
        for (int i = t; i < 64 * 20; i += 128) {
            int r = i / 20, q = i % 20;
            size_t base = (size_t)(b * S_ + k0 + r) * 960 + h * 20 + q;
            float4 kv = qkv4[base + 320];
            float* kd = &Kf[(r * 4) * KV_ST + q];   // K[r][4q+e] -> (r*4+e)*21+q
            kd[0 * KV_ST] = f2tff(kv.x);
            kd[1 * KV_ST] = f2tff(kv.y);
            kd[2 * KV_ST] = f2tff(kv.z);
            kd[3 * KV_ST] = f2tff(kv.w);
            float4 vv = qkv4[base + 640];
            // V row-major: float4 store, conflict-free (22r+q f4-banks)
            float4 vt = make_float4(f2tff(vv.x), f2tff(vv.y),
                                    f2tff(vv.z), f2tff(vv.w));
            *(float4*)&Vs[r * VS_ST + q * 4] = vt;
        }
        __syncthreads();

        // ---- S = Q K^T ----
        float s[8][4];
#pragma unroll
        for (int j = 0; j < 8; ++j)
#pragma unroll
            for (int q = 0; q < 4; ++q) s[j][q] = 0.f;
#pragma unroll
        for (int kt = 0; kt < 10; ++kt)
#pragma unroll
            for (int j = 0; j < 8; ++j) {
                const float* kb = &Kf[((j * 8 + g) * 4 + c) * KV_ST + 2 * kt];
                mma_tf32(s[j], qf[kt],
                         __float_as_uint(kb[0]), __float_as_uint(kb[1]));
            }

        // ---- causal mask (diagonal tile only) ----
        if (k0 == q0) {
            const int row0 = wq * 16 + g;
#pragma unroll
            for (int j = 0; j < 8; ++j) {
                const int col = j * 8 + 2 * c;
                if (col     > row0)     s[j][0] = -INFINITY;
                if (col + 1 > row0)     s[j][1] = -INFINITY;
                if (col     > row0 + 8) s[j][2] = -INFINITY;
                if (col + 1 > row0 + 8) s[j][3] = -INFINITY;
            }
        }

        // ---- online softmax (rows g, g+8; quad shuffles) ----
        float tm0 = -INFINITY, tm1 = -INFINITY;
#pragma unroll
        for (int j = 0; j < 8; ++j) {
            tm0 = fmaxf(tm0, fmaxf(s[j][0], s[j][1]));
            tm1 = fmaxf(tm1, fmaxf(s[j][2], s[j][3]));
        }
        tm0 = fmaxf(tm0, __shfl_xor_sync(0xffffffff, tm0, 1));
        tm0 = fmaxf(tm0, __shfl_xor_sync(0xffffffff, tm0, 2));
        tm1 = fmaxf(tm1, __shfl_xor_sync(0xffffffff, tm1, 1));
        tm1 = fmaxf(tm1, __shfl_xor_sync(0xffffffff, tm1, 2));
        float nm0 = fmaxf(m0, tm0), nm1 = fmaxf(m1, tm1);
        float cr0 = __expf(m0 - nm0), cr1 = __expf(m1 - nm1);
        m0 = nm0; m1 = nm1;
        float ls0 = 0.f, ls1 = 0.f;
#pragma unroll
        for (int j = 0; j < 8; ++j) {
            s[j][0] = __expf(s[j][0] - m0);
            s[j][1] = __expf(s[j][1] - m0);
            s[j][2] = __expf(s[j][2] - m1);
            s[j][3] = __expf(s[j][3] - m1);
            ls0 += s[j][0] + s[j][1];
            ls1 += s[j][2] + s[j][3];
        }
        ls0 += __shfl_xor_sync(0xffffffff, ls0, 1);
        ls0 += __shfl_xor_sync(0xffffffff, ls0, 2);
        ls1 += __shfl_xor_sync(0xffffffff, ls1, 1);
        ls1 += __shfl_xor_sync(0xffffffff, ls1, 2);
        l0 = l0 * cr0 + ls0;
        l1 = l1 * cr1 + ls1;
#pragma unroll
        for (int j = 0; j < 10; ++j) {
            o[j][0] *= cr0; o[j][1] *= cr0;
            o[j][2] *= cr1; o[j][3] *= cr1;
        }

        // ---- P round trip: C-fragment -> warp smem -> A-fragment ----
        __syncwarp();
#pragma unroll
        for (int j = 0; j < 8; ++j) {
            *(float2*)&Pw[g * P_ST + j * 8 + 2 * c] =
                make_float2(f2tff(s[j][0]), f2tff(s[j][1]));
            *(float2*)&Pw[(g + 8) * P_ST + j * 8 + 2 * c] =
                make_float2(f2tff(s[j][2]), f2tff(s[j][3]));
        }
        __syncwarp();
        unsigned pa[8][4];
#pragma unroll
        for (int kt = 0; kt < 8; ++kt) {
            const float* pp = &Pw[g * P_ST + kt * 8 + c];
            pa[kt][0] = __float_as_uint(pp[0]);
            pa[kt][1] = __float_as_uint(pp[8 * P_ST]);
            pa[kt][2] = __float_as_uint(pp[4]);
            pa[kt][3] = __float_as_uint(pp[8 * P_ST + 4]);
        }

        // ---- O += P V (V row-major; b0=V[8kt+c][n], b1=V[8kt+c+4][n]) ----
#pragma unroll
        for (int kt = 0; kt < 8; ++kt)
#pragma unroll
            for (int j = 0; j < 10; ++j) {
                const int n = j * 8 + g;
                const float* vb = &Vs[(kt * 8 + c) * VS_ST + n];
                mma_tf32(o[j], pa[kt],
                         __float_as_uint(vb[0]),
                         __float_as_uint(vb[4 * VS_ST]));
            }
    }

    // ---- epilogue: normalize, write g_attn ----
    const float inv0 = 1.f / l0, inv1 = 1.f / l1;
    const int r0 = q0 + wq * 16 + g;
    float* outp = g_attn + (size_t)(b * S_ + r0) * (H_ * HD_) + h * HD_;
#pragma unroll
    for (int j = 0; j < 10; ++j) {
        *(float2*)&outp[j * 8 + 2 * c] =
            make_float2(o[j][0] * inv0, o[j][1] * inv0);
        *(float2*)&outp[(size_t)8 * (H_ * HD_) + j * 8 + 2 * c] =
            make_float2(o[j][2] * inv1, o[j][3] * inv1);
    }
}

// ---------------------------------------------------------------------------
// Launch
// ---------------------------------------------------------------------------
extern "C" void kernel_launch(void* const* d_in, const int* in_sizes, int n_in,
                              void* d_out, int out_size) {
    const float* hidden  = (const float*)d_in[0];
    // d_in[1] = attention_mask: pure causal, implemented structurally
    const float* scaling = (const float*)d_in[2];
    const float* qkv_w   = (const float*)d_in[3];
    const float* qkv_b   = (const float*)d_in[4];
    const float* o_w     = (const float*)d_in[5];
    const float* o_b     = (const float*)d_in[6];
    float* out = (float*)d_out;

    void* p_qkv = nullptr;
    void* p_attn = nullptr;
    cudaGetSymbolAddress(&p_qkv, g_qkv);
    cudaGetSymbolAddress(&p_attn, g_attn);

    qscale_kernel<<<1, 128>>>(scaling);

    // QKV projection: [8192,1280] x [3840,1280]^T (+bias, Q-scale epilogue)
    gemm_tf32<1><<<dim3(NQKV / 128, (B_ * S_) / 128), 256>>>(
        hidden, qkv_w, qkv_b, (float*)p_qkv, B_ * S_, NQKV, D_);

    // Tensor-core causal flash attention
    const int smem_bytes = FL_SMEM_FLOATS * 4;   // 65536 B
    cudaFuncSetAttribute(flash_tc,
                         cudaFuncAttributeMaxDynamicSharedMemorySize, smem_bytes);
    flash_tc<<<dim3(S_ / 64, H_, B_), 128, smem_bytes>>>();

    // Output projection: [8192,1280] x [1280,1280]^T (+bias)
    gemm_tf32<0><<<dim3(D_ / 128, (B_ * S_) / 128), 256>>>(
        (const float*)p_attn, o_w, o_b, out, B_ * S_, D_, D_);
}

// round 9
// speedup vs baseline: 1.1952x; 1.0768x over previous
#include <cuda_runtime.h>
#include <math.h>

#define B_  4
#define S_  2048
#define D_  1280
#define H_  16
#define HD_ 80
#define NQKV (3 * H_ * HD_)   // 3840

// Scratch (allocation-free rule: __device__ globals)
__device__ float g_qkv[(size_t)B_ * S_ * NQKV];        // 126 MB
__device__ float g_attn[(size_t)B_ * S_ * H_ * HD_];   // 42 MB
__device__ float g_qscale[HD_];

// ---------------------------------------------------------------------------
// Helpers: tf32 rounding + mma
// ---------------------------------------------------------------------------
__device__ __forceinline__ unsigned f2tf(float x) {
    unsigned r;
    asm("cvt.rna.tf32.f32 %0, %1;" : "=r"(r) : "f"(x));
    return r;
}
__device__ __forceinline__ float f2tff(float x) {
    return __uint_as_float(f2tf(x));
}
__device__ __forceinline__ void mma_tf32(float* d, const unsigned* a,
                                         unsigned b0, unsigned b1) {
    asm volatile(
        "mma.sync.aligned.m16n8k8.row.col.f32.tf32.tf32.f32 "
        "{%0,%1,%2,%3}, {%4,%5,%6,%7}, {%8,%9}, {%0,%1,%2,%3};"
        : "+f"(d[0]), "+f"(d[1]), "+f"(d[2]), "+f"(d[3])
        : "r"(a[0]), "r"(a[1]), "r"(a[2]), "r"(a[3]), "r"(b0), "r"(b1));
}

// ---------------------------------------------------------------------------
// Per-dim query scale: softplus(scaling) * log2(e) / sqrt(HD)
// ---------------------------------------------------------------------------
__global__ void qscale_kernel(const float* __restrict__ scaling) {
    int i = threadIdx.x;
    if (i < HD_) {
        float x = scaling[i];
        float sp = (x > 20.f) ? x : log1pf(expf(x));
        g_qscale[i] = sp * 1.4426950408889634f * rsqrtf((float)HD_);
    }
}

// ---------------------------------------------------------------------------
// TF32 tensor-core GEMM (R7 config — best measured: 301.8us on O proj):
// C = A·B^T + bias, both K-major. 128x128 tile, KT=16, 256 threads,
// warp tile 32x64, m16n8k8.tf32. Double-buffered smem, SMS=136 layout
// ([k][row], conflict-free scalar fragment LDS at banks 8c+g).
// ---------------------------------------------------------------------------
#define SMS 136
#define STAGE (16 * SMS)   // floats per stage per operand

template <int APPLY_QSCALE>
__global__ __launch_bounds__(256, 2)
void gemm_tf32(const float* __restrict__ A, const float* __restrict__ Bm,
               const float* __restrict__ bias, float* __restrict__ C,
               int M, int N, int K) {
    __shared__ float As[2 * STAGE];
    __shared__ float Bs[2 * STAGE];

    const int tid  = threadIdx.x;
    const int lane = tid & 31;
    const int wid  = tid >> 5;
    const int wm   = wid & 3;
    const int wn   = wid >> 2;
    const int g    = lane >> 2;
    const int c    = lane & 3;

    const int m0 = blockIdx.y * 128;
    const int n0 = blockIdx.x * 128;

    const int lrow = tid >> 1;
    const int lc   = (tid & 1) * 8;

    const float* Ap = A  + (size_t)(m0 + lrow) * K + lc;
    const float* Bp = Bm + (size_t)(n0 + lrow) * K + lc;

    float acc[2][8][4];
#pragma unroll
    for (int i = 0; i < 2; ++i)
#pragma unroll
        for (int j = 0; j < 8; ++j)
#pragma unroll
            for (int q = 0; q < 4; ++q) acc[i][j][q] = 0.f;

    // load + store tile 0 into stage 0
    float4 pa0 = *(const float4*)(Ap + 0);
    float4 pa1 = *(const float4*)(Ap + 4);
    float4 pb0 = *(const float4*)(Bp + 0);
    float4 pb1 = *(const float4*)(Bp + 4);
    {
        float* as = &As[lc * SMS + lrow];
        as[0 * SMS] = f2tff(pa0.x); as[1 * SMS] = f2tff(pa0.y);
        as[2 * SMS] = f2tff(pa0.z); as[3 * SMS] = f2tff(pa0.w);
        as[4 * SMS] = f2tff(pa1.x); as[5 * SMS] = f2tff(pa1.y);
        as[6 * SMS] = f2tff(pa1.z); as[7 * SMS] = f2tff(pa1.w);
        float* bs = &Bs[lc * SMS + lrow];
        bs[0 * SMS] = f2tff(pb0.x); bs[1 * SMS] = f2tff(pb0.y);
        bs[2 * SMS] = f2tff(pb0.z); bs[3 * SMS] = f2tff(pb0.w);
        bs[4 * SMS] = f2tff(pb1.x); bs[5 * SMS] = f2tff(pb1.y);
        bs[6 * SMS] = f2tff(pb1.z); bs[7 * SMS] = f2tff(pb1.w);
    }
    __syncthreads();

    int p = 0;
    for (int k0 = 0; k0 < K; k0 += 16) {
        const bool more = (k0 + 16) < K;
        if (more) {   // prefetch next tile into registers
            pa0 = *(const float4*)(Ap + k0 + 16);
            pa1 = *(const float4*)(Ap + k0 + 20);
            pb0 = *(const float4*)(Bp + k0 + 16);
            pb1 = *(const float4*)(Bp + k0 + 20);
        }

        const float* Asp = &As[p * STAGE];
        const float* Bsp = &Bs[p * STAGE];
#pragma unroll
        for (int ks = 0; ks < 2; ++ks) {
            const int kk = ks * 8;
            unsigned af[2][4];
#pragma unroll
            for (int i = 0; i < 2; ++i) {
                const float* ab = &Asp[(kk + c) * SMS + wm * 32 + i * 16 + g];
                af[i][0] = __float_as_uint(ab[0]);
                af[i][1] = __float_as_uint(ab[8]);
                af[i][2] = __float_as_uint(ab[4 * SMS]);
                af[i][3] = __float_as_uint(ab[4 * SMS + 8]);
            }
#pragma unroll
            for (int j = 0; j < 8; ++j) {
                const float* bb = &Bsp[(kk + c) * SMS + wn * 64 + j * 8 + g];
                unsigned b0 = __float_as_uint(bb[0]);
                unsigned b1 = __float_as_uint(bb[4 * SMS]);
                mma_tf32(acc[0][j], af[0], b0, b1);
                mma_tf32(acc[1][j], af[1], b0, b1);
            }
        }

        if (more) {   // store prefetched tile into the inactive stage
            float* as = &As[(p ^ 1) * STAGE + lc * SMS + lrow];
            as[0 * SMS] = f2tff(pa0.x); as[1 * SMS] = f2tff(pa0.y);
            as[2 * SMS] = f2tff(pa0.z); as[3 * SMS] = f2tff(pa0.w);
            as[4 * SMS] = f2tff(pa1.x); as[5 * SMS] = f2tff(pa1.y);
            as[6 * SMS] = f2tff(pa1.z); as[7 * SMS] = f2tff(pa1.w);
            float* bs = &Bs[(p ^ 1) * STAGE + lc * SMS + lrow];
            bs[0 * SMS] = f2tff(pb0.x); bs[1 * SMS] = f2tff(pb0.y);
            bs[2 * SMS] = f2tff(pb0.z); bs[3 * SMS] = f2tff(pb0.w);
            bs[4 * SMS] = f2tff(pb1.x); bs[5 * SMS] = f2tff(pb1.y);
            bs[6 * SMS] = f2tff(pb1.z); bs[7 * SMS] = f2tff(pb1.w);
        }
        __syncthreads();
        p ^= 1;
    }

#pragma unroll
    for (int j = 0; j < 8; ++j) {
        const int col = n0 + wn * 64 + j * 8 + c * 2;
        float b0 = bias[col], b1 = bias[col + 1];
        float q0 = 1.f, q1 = 1.f;
        if (APPLY_QSCALE && col < H_ * HD_) {
            q0 = g_qscale[col % HD_];
            q1 = g_qscale[(col + 1) % HD_];
        }
#pragma unroll
        for (int i = 0; i < 2; ++i) {
            const int r0 = m0 + wm * 32 + i * 16 + g;
            float2 o0, o1;
            o0.x = (acc[i][j][0] + b0) * q0;
            o0.y = (acc[i][j][1] + b1) * q1;
            o1.x = (acc[i][j][2] + b0) * q0;
            o1.y = (acc[i][j][3] + b1) * q1;
            *(float2*)&C[(size_t)r0 * N + col]       = o0;
            *(float2*)&C[(size_t)(r0 + 8) * N + col] = o1;
        }
    }
}

// ---------------------------------------------------------------------------
// Tensor-core causal flash attention (R8 config — best measured).
// BQ=64 (4 warps x 16 rows), BK=64. K fragment-major stride 21 (conflict-
// free scalar LDS). V ROW-MAJOR stride 88: float4 STS (conflict-free),
// scalar fragment loads at banks 24c+g (all 32 distinct).
// grid = (S/64 [reversed], H, B), block = 128.
// ---------------------------------------------------------------------------
#define KV_ST 21
#define VS_ST 88
#define P_ST  68
#define QS_ST 84
#define QS_FLOATS (64 * QS_ST)          // 5376
#define KF_FLOATS (64 * 4 * KV_ST)      // 5376
#define VS_FLOATS (64 * VS_ST)          // 5632
#define FL_SMEM_FLOATS (QS_FLOATS + KF_FLOATS + VS_FLOATS)   // 16384

__global__ __launch_bounds__(128, 2)
void flash_tc() {
    extern __shared__ float sm[];
    float* Qs = sm;                     // [64][84]; reused as P
    float* Kf = sm + QS_FLOATS;
    float* Vs = Kf + KF_FLOATS;

    const int t    = threadIdx.x;
    const int lane = t & 31;
    const int wq   = t >> 5;
    const int g    = lane >> 2;
    const int c    = lane & 3;
    const int qt   = gridDim.x - 1 - blockIdx.x;   // heavy blocks first
    const int q0   = qt * 64;
    const int h    = blockIdx.y;
    const int b    = blockIdx.z;

    const float4* qkv4 = (const float4*)g_qkv;     // row stride 960

    // Stage Q (tf32-rounded) into Qs[64][84]
    for (int i = t; i < 64 * 20; i += 128) {
        int r = i / 20, q = i % 20;
        float4 v = qkv4[(size_t)(b * S_ + q0 + r) * 960 + h * 20 + q];
        float* dst = &Qs[r * QS_ST + q * 4];
        dst[0] = f2tff(v.x); dst[1] = f2tff(v.y);
        dst[2] = f2tff(v.z); dst[3] = f2tff(v.w);
    }
    __syncthreads();

    // Q fragments (A layout)
    unsigned qf[10][4];
#pragma unroll
    for (int kt = 0; kt < 10; ++kt) {
        const float* qp = &Qs[(wq * 16 + g) * QS_ST + kt * 8 + c];
        qf[kt][0] = __float_as_uint(qp[0]);
        qf[kt][1] = __float_as_uint(qp[8 * QS_ST]);
        qf[kt][2] = __float_as_uint(qp[4]);
        qf[kt][3] = __float_as_uint(qp[8 * QS_ST + 4]);
    }

    float m0 = -INFINITY, m1 = -INFINITY, l0 = 0.f, l1 = 0.f;
    float o[10][4];
#pragma unroll
    for (int j = 0; j < 10; ++j)
#pragma unroll
        for (int q = 0; q < 4; ++q) o[j][q] = 0.f;

    float* Pw = sm + wq * (16 * P_ST);   // warp-private, overlaps Qs (safe)

    const int ntiles = qt + 1;
    for (int kt0 = 0; kt0 < ntiles; ++kt0) {
        const int k0 = kt0 * 64;
        __syncthreads();
        for (int i = t; i < 64 * 20; i += 128) {
            int r = i / 20, q = i % 20;
            size_t base = (size_t)(b * S_ + k0 + r) * 960 + h * 20 + q;
            float4 kv = qkv4[base + 320];
            float* kd = &Kf[(r * 4) * KV_ST + q];   // K[r][4q+e] -> (r*4+e)*21+q
            kd[0 * KV_ST] = f2tff(kv.x);
            kd[1 * KV_ST] = f2tff(kv.y);
            kd[2 * KV_ST] = f2tff(kv.z);
            kd[3 * KV_ST] = f2tff(kv.w);
            float4 vv = qkv4[base + 640];
            // V row-major: float4 store, conflict-free
            float4 vt = make_float4(f2tff(vv.x), f2tff(vv.y),
                                    f2tff(vv.z), f2tff(vv.w));
            *(float4*)&Vs[r * VS_ST + q * 4] = vt;
        }
        __syncthreads();

        // ---- S = Q K^T ----
        float s[8][4];
#pragma unroll
        for (int j = 0; j < 8; ++j)
#pragma unroll
            for (int q = 0; q < 4; ++q) s[j][q] = 0.f;
#pragma unroll
        for (int kt = 0; kt < 10; ++kt)
#pragma unroll
            for (int j = 0; j < 8; ++j) {
                const float* kb = &Kf[((j * 8 + g) * 4 + c) * KV_ST + 2 * kt];
                mma_tf32(s[j], qf[kt],
                         __float_as_uint(kb[0]), __float_as_uint(kb[1]));
            }

        // ---- causal mask (diagonal tile only) ----
        if (k0 == q0) {
            const int row0 = wq * 16 + g;
#pragma unroll
            for (int j = 0; j < 8; ++j) {
                const int col = j * 8 + 2 * c;
                if (col     > row0)     s[j][0] = -INFINITY;
                if (col + 1 > row0)     s[j][1] = -INFINITY;
                if (col     > row0 + 8) s[j][2] = -INFINITY;
                if (col + 1 > row0 + 8) s[j][3] = -INFINITY;
            }
        }

        // ---- online softmax (rows g, g+8; quad shuffles) ----
        float tm0 = -INFINITY, tm1 = -INFINITY;
#pragma unroll
        for (int j = 0; j < 8; ++j) {
            tm0 = fmaxf(tm0, fmaxf(s[j][0], s[j][1]));
            tm1 = fmaxf(tm1, fmaxf(s[j][2], s[j][3]));
        }
        tm0 = fmaxf(tm0, __shfl_xor_sync(0xffffffff, tm0, 1));
        tm0 = fmaxf(tm0, __shfl_xor_sync(0xffffffff, tm0, 2));
        tm1 = fmaxf(tm1, __shfl_xor_sync(0xffffffff, tm1, 1));
        tm1 = fmaxf(tm1, __shfl_xor_sync(0xffffffff, tm1, 2));
        float nm0 = fmaxf(m0, tm0), nm1 = fmaxf(m1, tm1);
        float cr0 = __expf(m0 - nm0), cr1 = __expf(m1 - nm1);
        m0 = nm0; m1 = nm1;
        float ls0 = 0.f, ls1 = 0.f;
#pragma unroll
        for (int j = 0; j < 8; ++j) {
            s[j][0] = __expf(s[j][0] - m0);
            s[j][1] = __expf(s[j][1] - m0);
            s[j][2] = __expf(s[j][2] - m1);
            s[j][3] = __expf(s[j][3] - m1);
            ls0 += s[j][0] + s[j][1];
            ls1 += s[j][2] + s[j][3];
        }
        ls0 += __shfl_xor_sync(0xffffffff, ls0, 1);
        ls0 += __shfl_xor_sync(0xffffffff, ls0, 2);
        ls1 += __shfl_xor_sync(0xffffffff, ls1, 1);
        ls1 += __shfl_xor_sync(0xffffffff, ls1, 2);
        l0 = l0 * cr0 + ls0;
        l1 = l1 * cr1 + ls1;
#pragma unroll
        for (int j = 0; j < 10; ++j) {
            o[j][0] *= cr0; o[j][1] *= cr0;
            o[j][2] *= cr1; o[j][3] *= cr1;
        }

        // ---- P round trip: C-fragment -> warp smem -> A-fragment ----
        __syncwarp();
#pragma unroll
        for (int j = 0; j < 8; ++j) {
            *(float2*)&Pw[g * P_ST + j * 8 + 2 * c] =
                make_float2(f2tff(s[j][0]), f2tff(s[j][1]));
            *(float2*)&Pw[(g + 8) * P_ST + j * 8 + 2 * c] =
                make_float2(f2tff(s[j][2]), f2tff(s[j][3]));
        }
        __syncwarp();
        unsigned pa[8][4];
#pragma unroll
        for (int kt = 0; kt < 8; ++kt) {
            const float* pp = &Pw[g * P_ST + kt * 8 + c];
            pa[kt][0] = __float_as_uint(pp[0]);
            pa[kt][1] = __float_as_uint(pp[8 * P_ST]);
            pa[kt][2] = __float_as_uint(pp[4]);
            pa[kt][3] = __float_as_uint(pp[8 * P_ST + 4]);
        }

        // ---- O += P V (V row-major; b0=V[8kt+c][n], b1=V[8kt+c+4][n]) ----
#pragma unroll
        for (int kt = 0; kt < 8; ++kt)
#pragma unroll
            for (int j = 0; j < 10; ++j) {
                const int n = j * 8 + g;
                const float* vb = &Vs[(kt * 8 + c) * VS_ST + n];
                mma_tf32(o[j], pa[kt],
                         __float_as_uint(vb[0]),
                         __float_as_uint(vb[4 * VS_ST]));
            }
    }

    // ---- epilogue: normalize, write g_attn ----
    const float inv0 = 1.f / l0, inv1 = 1.f / l1;
    const int r0 = q0 + wq * 16 + g;
    float* outp = g_attn + (size_t)(b * S_ + r0) * (H_ * HD_) + h * HD_;
#pragma unroll
    for (int j = 0; j < 10; ++j) {
        *(float2*)&outp[j * 8 + 2 * c] =
            make_float2(o[j][0] * inv0, o[j][1] * inv0);
        *(float2*)&outp[(size_t)8 * (H_ * HD_) + j * 8 + 2 * c] =
            make_float2(o[j][2] * inv1, o[j][3] * inv1);
    }
}

// ---------------------------------------------------------------------------
// Launch
// ---------------------------------------------------------------------------
extern "C" void kernel_launch(void* const* d_in, const int* in_sizes, int n_in,
                              void* d_out, int out_size) {
    const float* hidden  = (const float*)d_in[0];
    // d_in[1] = attention_mask: pure causal, implemented structurally
    const float* scaling = (const float*)d_in[2];
    const float* qkv_w   = (const float*)d_in[3];
    const float* qkv_b   = (const float*)d_in[4];
    const float* o_w     = (const float*)d_in[5];
    const float* o_b     = (const float*)d_in[6];
    float* out = (float*)d_out;

    void* p_qkv = nullptr;
    void* p_attn = nullptr;
    cudaGetSymbolAddress(&p_qkv, g_qkv);
    cudaGetSymbolAddress(&p_attn, g_attn);

    qscale_kernel<<<1, 128>>>(scaling);

    // QKV projection: [8192,1280] x [3840,1280]^T (+bias, Q-scale epilogue)
    gemm_tf32<1><<<dim3(NQKV / 128, (B_ * S_) / 128), 256>>>(
        hidden, qkv_w, qkv_b, (float*)p_qkv, B_ * S_, NQKV, D_);

    // Tensor-core causal flash attention
    const int smem_bytes = FL_SMEM_FLOATS * 4;   // 65536 B
    cudaFuncSetAttribute(flash_tc,
                         cudaFuncAttributeMaxDynamicSharedMemorySize, smem_bytes);
    flash_tc<<<dim3(S_ / 64, H_, B_), 128, smem_bytes>>>();

    // Output projection: [8192,1280] x [1280,1280]^T (+bias)
    gemm_tf32<0><<<dim3(D_ / 128, (B_ * S_) / 128), 256>>>(
        (const float*)p_attn, o_w, o_b, out, B_ * S_, D_, D_);
}

// round 10
// speedup vs baseline: 1.4169x; 1.1855x over previous
#include <cuda_runtime.h>
#include <math.h>

#define B_  4
#define S_  2048
#define D_  1280
#define H_  16
#define HD_ 80
#define NQKV (3 * H_ * HD_)   // 3840

// Scratch (allocation-free rule: __device__ globals)
__device__ float g_qkv[(size_t)B_ * S_ * NQKV];        // 126 MB
__device__ float g_attn[(size_t)B_ * S_ * H_ * HD_];   // 42 MB (tf32-rounded)
__device__ float g_hid[(size_t)B_ * S_ * D_];          // 42 MB (tf32-rounded)
__device__ float g_qkvw[(size_t)NQKV * D_];            // 19.7 MB (tf32-rounded)
__device__ float g_ow[(size_t)D_ * (H_ * HD_)];        // 6.6 MB (tf32-rounded)
__device__ float g_qscale[HD_];

// ---------------------------------------------------------------------------
// Helpers
// ---------------------------------------------------------------------------
__device__ __forceinline__ unsigned f2tf(float x) {
    unsigned r;
    asm("cvt.rna.tf32.f32 %0, %1;" : "=r"(r) : "f"(x));
    return r;
}
__device__ __forceinline__ float f2tff(float x) {
    return __uint_as_float(f2tf(x));
}
__device__ __forceinline__ void mma_tf32(float* d, const unsigned* a,
                                         unsigned b0, unsigned b1) {
    asm volatile(
        "mma.sync.aligned.m16n8k8.row.col.f32.tf32.tf32.f32 "
        "{%0,%1,%2,%3}, {%4,%5,%6,%7}, {%8,%9}, {%0,%1,%2,%3};"
        : "+f"(d[0]), "+f"(d[1]), "+f"(d[2]), "+f"(d[3])
        : "r"(a[0]), "r"(a[1]), "r"(a[2]), "r"(a[3]), "r"(b0), "r"(b1));
}
__device__ __forceinline__ void cp_async16(unsigned dst, const float* src) {
    asm volatile("cp.async.cg.shared.global [%0], [%1], 16;"
                 :: "r"(dst), "l"(src));
}
__device__ __forceinline__ void cp_commit() {
    asm volatile("cp.async.commit_group;");
}
template <int N>
__device__ __forceinline__ void cp_wait() {
    asm volatile("cp.async.wait_group %0;" :: "n"(N));
}

// ---------------------------------------------------------------------------
// Pre-pass: tf32-round an fp32 array (element count divisible by 4)
// ---------------------------------------------------------------------------
__global__ void cvt_tf32_kernel(const float* __restrict__ src,
                                float* __restrict__ dst, int n4) {
    int i = blockIdx.x * blockDim.x + threadIdx.x;
    if (i < n4) {
        float4 v = ((const float4*)src)[i];
        ((float4*)dst)[i] = make_float4(f2tff(v.x), f2tff(v.y),
                                        f2tff(v.z), f2tff(v.w));
    }
}

// ---------------------------------------------------------------------------
// Per-dim query scale: softplus(scaling) * log2(e) / sqrt(HD)
// ---------------------------------------------------------------------------
__global__ void qscale_kernel(const float* __restrict__ scaling) {
    int i = threadIdx.x;
    if (i < HD_) {
        float x = scaling[i];
        float sp = (x > 20.f) ? x : log1pf(expf(x));
        g_qscale[i] = sp * 1.4426950408889634f * rsqrtf((float)HD_);
    }
}

// ---------------------------------------------------------------------------
// TF32 tensor-core GEMM, 4-stage cp.async pipeline.
// C = A·B^T + bias; A,B K-major and ALREADY tf32-rounded in gmem.
// 128x128 tile, KT=16/stage, 256 threads, warp tile 32x64, m16n8k8.
// smem row-major [row][k], stride 20: cp.async 16B contiguous stores;
// fragment LDS banks (20g+c) mod 32 all-distinct (A and B identical form).
// ---------------------------------------------------------------------------
#define GST  20
#define GSTG (128 * GST)            // 2560 floats per operand-stage
#define NSTG 4
#define GEMM_SMEM (2 * NSTG * GSTG * 4)   // 81920 B

template <int APPLY_QSCALE>
__global__ __launch_bounds__(256, 2)
void gemm_tf32(const float* __restrict__ A, const float* __restrict__ Bm,
               const float* __restrict__ bias, float* __restrict__ C,
               int M, int N, int K) {
    extern __shared__ float gsm[];
    float* smA = gsm;                    // [NSTG][128][GST]
    float* smB = gsm + NSTG * GSTG;

    const int tid  = threadIdx.x;
    const int lane = tid & 31;
    const int wid  = tid >> 5;
    const int wm   = wid & 3;
    const int wn   = wid >> 2;
    const int g    = lane >> 2;
    const int c    = lane & 3;

    const int m0 = blockIdx.y * 128;
    const int n0 = blockIdx.x * 128;

    const int lrow = tid >> 1;       // 0..127
    const int lc   = (tid & 1) * 8;  // 0 or 8

    const float* Ap = A  + (size_t)(m0 + lrow) * K + lc;
    const float* Bp = Bm + (size_t)(n0 + lrow) * K + lc;

    const unsigned sA = (unsigned)__cvta_generic_to_shared(smA)
                        + (lrow * GST + lc) * 4;
    const unsigned sB = (unsigned)__cvta_generic_to_shared(smB)
                        + (lrow * GST + lc) * 4;

    float acc[2][8][4];
#pragma unroll
    for (int i = 0; i < 2; ++i)
#pragma unroll
        for (int j = 0; j < 8; ++j)
#pragma unroll
            for (int q = 0; q < 4; ++q) acc[i][j][q] = 0.f;

    const int tiles = K >> 4;

    // prologue: stages 0..2
#pragma unroll
    for (int s = 0; s < NSTG - 1; ++s) {
        const int k0 = s * 16;
        cp_async16(sA + s * GSTG * 4,      Ap + k0);
        cp_async16(sA + s * GSTG * 4 + 16, Ap + k0 + 4);
        cp_async16(sB + s * GSTG * 4,      Bp + k0);
        cp_async16(sB + s * GSTG * 4 + 16, Bp + k0 + 4);
        cp_commit();
    }

    for (int i = 0; i < tiles; ++i) {
        cp_wait<NSTG - 2>();
        __syncthreads();

        const int st = i & (NSTG - 1);
        const float* Asp = &smA[st * GSTG];
        const float* Bsp = &smB[st * GSTG];
#pragma unroll
        for (int ks = 0; ks < 2; ++ks) {
            const int kk = ks * 8;
            unsigned af[2][4];
#pragma unroll
            for (int ii = 0; ii < 2; ++ii) {
                const float* ab = &Asp[(wm * 32 + ii * 16 + g) * GST + kk + c];
                af[ii][0] = __float_as_uint(ab[0]);
                af[ii][1] = __float_as_uint(ab[8 * GST]);
                af[ii][2] = __float_as_uint(ab[4]);
                af[ii][3] = __float_as_uint(ab[8 * GST + 4]);
            }
#pragma unroll
            for (int j = 0; j < 8; ++j) {
                const float* bb = &Bsp[(wn * 64 + j * 8 + g) * GST + kk + c];
                unsigned b0 = __float_as_uint(bb[0]);
                unsigned b1 = __float_as_uint(bb[4]);
                mma_tf32(acc[0][j], af[0], b0, b1);
                mma_tf32(acc[1][j], af[1], b0, b1);
            }
        }

        const int nf = i + NSTG - 1;
        if (nf < tiles) {
            const int ns = nf & (NSTG - 1);
            const int k0 = nf * 16;
            cp_async16(sA + ns * GSTG * 4,      Ap + k0);
            cp_async16(sA + ns * GSTG * 4 + 16, Ap + k0 + 4);
            cp_async16(sB + ns * GSTG * 4,      Bp + k0);
            cp_async16(sB + ns * GSTG * 4 + 16, Bp + k0 + 4);
        }
        cp_commit();
    }

    // Epilogue: + bias, optional Q scaling, float2 stores
#pragma unroll
    for (int j = 0; j < 8; ++j) {
        const int col = n0 + wn * 64 + j * 8 + c * 2;
        float b0 = bias[col], b1 = bias[col + 1];
        float q0 = 1.f, q1 = 1.f;
        if (APPLY_QSCALE && col < H_ * HD_) {
            q0 = g_qscale[col % HD_];
            q1 = g_qscale[(col + 1) % HD_];
        }
#pragma unroll
        for (int i = 0; i < 2; ++i) {
            const int r0 = m0 + wm * 32 + i * 16 + g;
            float2 o0, o1;
            o0.x = (acc[i][j][0] + b0) * q0;
            o0.y = (acc[i][j][1] + b1) * q1;
            o1.x = (acc[i][j][2] + b0) * q0;
            o1.y = (acc[i][j][3] + b1) * q1;
            *(float2*)&C[(size_t)r0 * N + col]       = o0;
            *(float2*)&C[(size_t)(r0 + 8) * N + col] = o1;
        }
    }
}

// ---------------------------------------------------------------------------
// Tensor-core causal flash attention (R8/R9 config — best measured).
// Epilogue now tf32-rounds its output so the O-projection can cp.async it
// raw (bit-identical to R9's load-time rounding).
// ---------------------------------------------------------------------------
#define KV_ST 21
#define VS_ST 88
#define P_ST  68
#define QS_ST 84
#define QS_FLOATS (64 * QS_ST)          // 5376
#define KF_FLOATS (64 * 4 * KV_ST)      // 5376
#define VS_FLOATS (64 * VS_ST)          // 5632
#define FL_SMEM_FLOATS (QS_FLOATS + KF_FLOATS + VS_FLOATS)   // 16384

__global__ __launch_bounds__(128, 2)
void flash_tc() {
    extern __shared__ float sm[];
    float* Qs = sm;                     // [64][84]; reused as P
    float* Kf = sm + QS_FLOATS;
    float* Vs = Kf + KF_FLOATS;

    const int t    = threadIdx.x;
    const int lane = t & 31;
    const int wq   = t >> 5;
    const int g    = lane >> 2;
    const int c    = lane & 3;
    const int qt   = gridDim.x - 1 - blockIdx.x;   // heavy blocks first
    const int q0   = qt * 64;
    const int h    = blockIdx.y;
    const int b    = blockIdx.z;

    const float4* qkv4 = (const float4*)g_qkv;     // row stride 960

    // Stage Q (tf32-rounded) into Qs[64][84]
    for (int i = t; i < 64 * 20; i += 128) {
        int r = i / 20, q = i % 20;
        float4 v = qkv4[(size_t)(b * S_ + q0 + r) * 960 + h * 20 + q];
        float* dst = &Qs[r * QS_ST + q * 4];
        dst[0] = f2tff(v.x); dst[1] = f2tff(v.y);
        dst[2] = f2tff(v.z); dst[3] = f2tff(v.w);
    }
    __syncthreads();

    // Q fragments (A layout)
    unsigned qf[10][4];
#pragma unroll
    for (int kt = 0; kt < 10; ++kt) {
        const float* qp = &Qs[(wq * 16 + g) * QS_ST + kt * 8 + c];
        qf[kt][0] = __float_as_uint(qp[0]);
        qf[kt][1] = __float_as_uint(qp[8 * QS_ST]);
        qf[kt][2] = __float_as_uint(qp[4]);
        qf[kt][3] = __float_as_uint(qp[8 * QS_ST + 4]);
    }

    float m0 = -INFINITY, m1 = -INFINITY, l0 = 0.f, l1 = 0.f;
    float o[10][4];
#pragma unroll
    for (int j = 0; j < 10; ++j)
#pragma unroll
        for (int q = 0; q < 4; ++q) o[j][q] = 0.f;

    float* Pw = sm + wq * (16 * P_ST);   // warp-private, overlaps Qs (safe)

    const int ntiles = qt + 1;
    for (int kt0 = 0; kt0 < ntiles; ++kt0) {
        const int k0 = kt0 * 64;
        __syncthreads();
        for (int i = t; i < 64 * 20; i += 128) {
            int r = i / 20, q = i % 20;
            size_t base = (size_t)(b * S_ + k0 + r) * 960 + h * 20 + q;
            float4 kv = qkv4[base + 320];
            float* kd = &Kf[(r * 4) * KV_ST + q];   // K[r][4q+e] -> (r*4+e)*21+q
            kd[0 * KV_ST] = f2tff(kv.x);
            kd[1 * KV_ST] = f2tff(kv.y);
            kd[2 * KV_ST] = f2tff(kv.z);
            kd[3 * KV_ST] = f2tff(kv.w);
            float4 vv = qkv4[base + 640];
            // V row-major: float4 store, conflict-free
            float4 vt = make_float4(f2tff(vv.x), f2tff(vv.y),
                                    f2tff(vv.z), f2tff(vv.w));
            *(float4*)&Vs[r * VS_ST + q * 4] = vt;
        }
        __syncthreads();

        // ---- S = Q K^T ----
        float s[8][4];
#pragma unroll
        for (int j = 0; j < 8; ++j)
#pragma unroll
            for (int q = 0; q < 4; ++q) s[j][q] = 0.f;
#pragma unroll
        for (int kt = 0; kt < 10; ++kt)
#pragma unroll
            for (int j = 0; j < 8; ++j) {
                const float* kb = &Kf[((j * 8 + g) * 4 + c) * KV_ST + 2 * kt];
                mma_tf32(s[j], qf[kt],
                         __float_as_uint(kb[0]), __float_as_uint(kb[1]));
            }

        // ---- causal mask (diagonal tile only) ----
        if (k0 == q0) {
            const int row0 = wq * 16 + g;
#pragma unroll
            for (int j = 0; j < 8; ++j) {
                const int col = j * 8 + 2 * c;
                if (col     > row0)     s[j][0] = -INFINITY;
                if (col + 1 > row0)     s[j][1] = -INFINITY;
                if (col     > row0 + 8) s[j][2] = -INFINITY;
                if (col + 1 > row0 + 8) s[j][3] = -INFINITY;
            }
        }

        // ---- online softmax (rows g, g+8; quad shuffles) ----
        float tm0 = -INFINITY, tm1 = -INFINITY;
#pragma unroll
        for (int j = 0; j < 8; ++j) {
            tm0 = fmaxf(tm0, fmaxf(s[j][0], s[j][1]));
            tm1 = fmaxf(tm1, fmaxf(s[j][2], s[j][3]));
        }
        tm0 = fmaxf(tm0, __shfl_xor_sync(0xffffffff, tm0, 1));
        tm0 = fmaxf(tm0, __shfl_xor_sync(0xffffffff, tm0, 2));
        tm1 = fmaxf(tm1, __shfl_xor_sync(0xffffffff, tm1, 1));
        tm1 = fmaxf(tm1, __shfl_xor_sync(0xffffffff, tm1, 2));
        float nm0 = fmaxf(m0, tm0), nm1 = fmaxf(m1, tm1);
        float cr0 = __expf(m0 - nm0), cr1 = __expf(m1 - nm1);
        m0 = nm0; m1 = nm1;
        float ls0 = 0.f, ls1 = 0.f;
#pragma unroll
        for (int j = 0; j < 8; ++j) {
            s[j][0] = __expf(s[j][0] - m0);
            s[j][1] = __expf(s[j][1] - m0);
            s[j][2] = __expf(s[j][2] - m1);
            s[j][3] = __expf(s[j][3] - m1);
            ls0 += s[j][0] + s[j][1];
            ls1 += s[j][2] + s[j][3];
        }
        ls0 += __shfl_xor_sync(0xffffffff, ls0, 1);
        ls0 += __shfl_xor_sync(0xffffffff, ls0, 2);
        ls1 += __shfl_xor_sync(0xffffffff, ls1, 1);
        ls1 += __shfl_xor_sync(0xffffffff, ls1, 2);
        l0 = l0 * cr0 + ls0;
        l1 = l1 * cr1 + ls1;
#pragma unroll
        for (int j = 0; j < 10; ++j) {
            o[j][0] *= cr0; o[j][1] *= cr0;
            o[j][2] *= cr1; o[j][3] *= cr1;
        }

        // ---- P round trip: C-fragment -> warp smem -> A-fragment ----
        __syncwarp();
#pragma unroll
        for (int j = 0; j < 8; ++j) {
            *(float2*)&Pw[g * P_ST + j * 8 + 2 * c] =
                make_float2(f2tff(s[j][0]), f2tff(s[j][1]));
            *(float2*)&Pw[(g + 8) * P_ST + j * 8 + 2 * c] =
                make_float2(f2tff(s[j][2]), f2tff(s[j][3]));
        }
        __syncwarp();
        unsigned pa[8][4];
#pragma unroll
        for (int kt = 0; kt < 8; ++kt) {
            const float* pp = &Pw[g * P_ST + kt * 8 + c];
            pa[kt][0] = __float_as_uint(pp[0]);
            pa[kt][1] = __float_as_uint(pp[8 * P_ST]);
            pa[kt][2] = __float_as_uint(pp[4]);
            pa[kt][3] = __float_as_uint(pp[8 * P_ST + 4]);
        }

        // ---- O += P V (V row-major; b0=V[8kt+c][n], b1=V[8kt+c+4][n]) ----
#pragma unroll
        for (int kt = 0; kt < 8; ++kt)
#pragma unroll
            for (int j = 0; j < 10; ++j) {
                const int n = j * 8 + g;
                const float* vb = &Vs[(kt * 8 + c) * VS_ST + n];
                mma_tf32(o[j], pa[kt],
                         __float_as_uint(vb[0]),
                         __float_as_uint(vb[4 * VS_ST]));
            }
    }

    // ---- epilogue: normalize, tf32-round, write g_attn ----
    const float inv0 = 1.f / l0, inv1 = 1.f / l1;
    const int r0 = q0 + wq * 16 + g;
    float* outp = g_attn + (size_t)(b * S_ + r0) * (H_ * HD_) + h * HD_;
#pragma unroll
    for (int j = 0; j < 10; ++j) {
        *(float2*)&outp[j * 8 + 2 * c] =
            make_float2(f2tff(o[j][0] * inv0), f2tff(o[j][1] * inv0));
        *(float2*)&outp[(size_t)8 * (H_ * HD_) + j * 8 + 2 * c] =
            make_float2(f2tff(o[j][2] * inv1), f2tff(o[j][3] * inv1));
    }
}

// ---------------------------------------------------------------------------
// Launch
// ---------------------------------------------------------------------------
extern "C" void kernel_launch(void* const* d_in, const int* in_sizes, int n_in,
                              void* d_out, int out_size) {
    const float* hidden  = (const float*)d_in[0];
    // d_in[1] = attention_mask: pure causal, implemented structurally
    const float* scaling = (const float*)d_in[2];
    const float* qkv_w   = (const float*)d_in[3];
    const float* qkv_b   = (const float*)d_in[4];
    const float* o_w     = (const float*)d_in[5];
    const float* o_b     = (const float*)d_in[6];
    float* out = (float*)d_out;

    void *p_qkv, *p_attn, *p_hid, *p_qkvw, *p_ow;
    cudaGetSymbolAddress(&p_qkv, g_qkv);
    cudaGetSymbolAddress(&p_attn, g_attn);
    cudaGetSymbolAddress(&p_hid, g_hid);
    cudaGetSymbolAddress(&p_qkvw, g_qkvw);
    cudaGetSymbolAddress(&p_ow, g_ow);

    qscale_kernel<<<1, 128>>>(scaling);

    // Pre-round GEMM inputs to tf32 (RNA) — moves the conversion out of the
    // GEMM hot loop; numerics identical to converting at load time.
    {
        int n4;
        n4 = (B_ * S_ * D_) / 4;
        cvt_tf32_kernel<<<(n4 + 255) / 256, 256>>>(hidden, (float*)p_hid, n4);
        n4 = (NQKV * D_) / 4;
        cvt_tf32_kernel<<<(n4 + 255) / 256, 256>>>(qkv_w, (float*)p_qkvw, n4);
        n4 = (D_ * H_ * HD_) / 4;
        cvt_tf32_kernel<<<(n4 + 255) / 256, 256>>>(o_w, (float*)p_ow, n4);
    }

    cudaFuncSetAttribute(gemm_tf32<1>,
                         cudaFuncAttributeMaxDynamicSharedMemorySize, GEMM_SMEM);
    cudaFuncSetAttribute(gemm_tf32<0>,
                         cudaFuncAttributeMaxDynamicSharedMemorySize, GEMM_SMEM);

    // QKV projection: [8192,1280] x [3840,1280]^T (+bias, Q-scale epilogue)
    gemm_tf32<1><<<dim3(NQKV / 128, (B_ * S_) / 128), 256, GEMM_SMEM>>>(
        (const float*)p_hid, (const float*)p_qkvw, qkv_b,
        (float*)p_qkv, B_ * S_, NQKV, D_);

    // Tensor-core causal flash attention
    const int smem_bytes = FL_SMEM_FLOATS * 4;   // 65536 B
    cudaFuncSetAttribute(flash_tc,
                         cudaFuncAttributeMaxDynamicSharedMemorySize, smem_bytes);
    flash_tc<<<dim3(S_ / 64, H_, B_), 128, smem_bytes>>>();

    // Output projection: [8192,1280] x [1280,1280]^T (+bias)
    gemm_tf32<0><<<dim3(D_ / 128, (B_ * S_) / 128), 256, GEMM_SMEM>>>(
        (const float*)p_attn, (const float*)p_ow, o_b,
        out, B_ * S_, D_, D_);
}